// round 9
// baseline (speedup 1.0000x reference)
#include <cuda_runtime.h>
#include <cuda_fp16.h>
#include <cstdint>
#include <cmath>

// ---------------- problem constants ----------------
#define NTOK 8192      // B*T
#define DDIM 2048
#define NE   64

// output layout (concatenated float32)
#define P_OFF 0
#define I_OFF (NTOK * NE)
#define M_OFF (I_OFF + NTOK * 2)

// ---------------- GEMM tiling ----------------
// 128 CTAs x 512 thr; CTA = 128 tok x 128 col x (K/2).
// Two independent 256-thr groups per CTA: grp0 = gate cols, grp1 = noise cols.
// A (x) comes straight from gmem into mma fragments; only B lives in smem.
#define KSPLIT 2
#define KQ     1024            // K per split
#define CHK    32              // k per chunk
#define NCH    32              // chunks (KQ/CHK)
#define BROW   144             // B smem row stride (128B data + 16B pad)
#define B_PL   (32 * BROW)     // one plane: 32 k x 64 cols   (4608)
#define STG_SZ (2 * B_PL)      // H+L planes                  (9216)
#define GRP_SZ (2 * STG_SZ)    // double buffered             (18432)
#define SMEMB  (2 * GRP_SZ)    // two groups                  (36864)

// ---------------- scratch ----------------
__device__ float g_part[KSPLIT * NTOK * 128];   // k-split partials (8MB)
__device__ int   g_ctr[64];                     // per-tile arrival counters (self-resetting)

// ---------------- helpers ----------------
__device__ __forceinline__ uint32_t smem_u32(const void* p) {
    uint32_t a;
    asm("{ .reg .u64 t; cvta.to.shared.u64 t, %1; cvt.u32.u64 %0, t; }" : "=r"(a) : "l"(p));
    return a;
}
__device__ __forceinline__ void ldsm4t(uint32_t (&r)[4], uint32_t addr) {
    asm volatile("ldmatrix.sync.aligned.m8n8.x4.trans.shared.b16 {%0,%1,%2,%3}, [%4];"
                 : "=r"(r[0]), "=r"(r[1]), "=r"(r[2]), "=r"(r[3]) : "r"(addr));
}
__device__ __forceinline__ void mma16816(float (&c)[4], const uint32_t (&a)[4],
                                         uint32_t b0, uint32_t b1) {
    asm volatile(
        "mma.sync.aligned.m16n8k16.row.col.f32.f16.f16.f32 "
        "{%0,%1,%2,%3},{%4,%5,%6,%7},{%8,%9},{%0,%1,%2,%3};"
        : "+f"(c[0]), "+f"(c[1]), "+f"(c[2]), "+f"(c[3])
        : "r"(a[0]), "r"(a[1]), "r"(a[2]), "r"(a[3]), "r"(b0), "r"(b1));
}
__device__ __forceinline__ uint32_t h2_bits(__half2 v) {
    return *reinterpret_cast<uint32_t*>(&v);
}
// split one float2 -> hi half2 bits + lo (residual) half2 bits
__device__ __forceinline__ void split2h(float a, float b, uint32_t& H, uint32_t& L) {
    __half2 hp = __floats2half2_rn(a, b);
    float ra = a - __low2float(hp);
    float rb = b - __high2float(hp);
    __half2 lp = __floats2half2_rn(ra, rb);
    H = h2_bits(hp); L = h2_bits(lp);
}
// split 8 fp32 -> 2 planes of 8 fp16 (packed uint4 each)
__device__ __forceinline__ void split8h(const float* f, uint4& H, uint4& L) {
    uint32_t hw[4], lw[4];
    #pragma unroll
    for (int i = 0; i < 4; i++) split2h(f[2 * i], f[2 * i + 1], hw[i], lw[i]);
    H = make_uint4(hw[0], hw[1], hw[2], hw[3]);
    L = make_uint4(lw[0], lw[1], lw[2], lw[3]);
}
__device__ __forceinline__ float softplus_f(float v) {
    return (v > 20.0f) ? v : log1pf(expf(v));
}
__device__ __forceinline__ void top2_merge(float& v1, int& i1, float& v2, int& i2,
                                           float ov1, int oi1, float ov2, int oi2) {
    bool ow = (ov1 > v1) || (ov1 == v1 && oi1 < i1);
    float nv1 = ow ? ov1 : v1;  int ni1 = ow ? oi1 : i1;
    float lv  = ow ? v1  : ov1; int li  = ow ? i1  : oi1;
    float wv2 = ow ? ov2 : v2;  int wi2 = ow ? oi2 : i2;
    bool sw = (lv > wv2) || (lv == wv2 && li < wi2);
    v1 = nv1; i1 = ni1;
    v2 = sw ? lv : wv2; i2 = sw ? li : wi2;
}

// ---------------- fused GEMM + router ----------------
__global__ __launch_bounds__(512, 1) void gemm_fused(
    const float* __restrict__ x, const float* __restrict__ wg,
    const float* __restrict__ wn, const float* __restrict__ eps,
    float* __restrict__ out)
{
    extern __shared__ char smem[];
    __shared__ int s_flag;
    const int tid  = threadIdx.x;
    const int wid  = tid >> 5;      // 0..15
    const int lane = tid & 31;
    const int grp  = wid >> 3;      // 0=gate, 1=noise
    const int wg8  = wid & 7;
    const int gtid = tid & 255;
    const int tile = blockIdx.x >> 1;
    const int ks   = blockIdx.x & 1;
    const long t0  = (long)tile * 128;
    const int kbase = ks * KQ;

    const int m0 = (wg8 & 3) * 32;     // warp m-group (4)
    const int n0 = (wg8 >> 2) * 32;    // warp n-group (2) within group's 64 cols

    char* gBp = smem + grp * GRP_SZ;
    const uint32_t gB = smem_u32(gBp);
    const float* wsel = grp ? wn : wg;

    // B fill indices
    const int bkk = gtid >> 3;         // k row 0..31
    const int bn0 = (gtid & 7) * 8;    // 8 experts

    // A fragment LDG base: row = t0 + m0 + lane/4, k = kbase + (lane%4)*2
    const float* xbase = x + (t0 + m0 + (lane >> 2)) * DDIM + kbase + (lane & 3) * 2;

    const uint32_t b_lane = (uint32_t)((lane & 15) * BROW + (lane >> 4) * 16);

    float acc[2][4][4];
    #pragma unroll
    for (int a = 0; a < 2; a++)
        #pragma unroll
        for (int b = 0; b < 4; b++)
            #pragma unroll
            for (int c = 0; c < 4; c++) acc[a][b][c] = 0.0f;

    float4 swa, swb;   // staged B chunk

    #define GBAR() asm volatile("bar.sync %0, 256;" :: "r"(grp + 1) : "memory")

    #define LOAD_B(ch) do {                                                            \
        const float4* pw = reinterpret_cast<const float4*>(                            \
            wsel + (long)(kbase + (ch) * CHK + bkk) * 64 + bn0);                       \
        swa = pw[0]; swb = pw[1];                                                      \
    } while (0)

    #define STORE_B(stg) do {                                                          \
        uint4 H, L;                                                                    \
        float f[8] = {swa.x, swa.y, swa.z, swa.w, swb.x, swb.y, swb.z, swb.w};         \
        split8h(f, H, L);                                                              \
        *reinterpret_cast<uint4*>(gBp + (stg) * STG_SZ + bkk * BROW + bn0 * 2) = H;    \
        *reinterpret_cast<uint4*>(gBp + (stg) * STG_SZ + B_PL + bkk * BROW + bn0 * 2) = L; \
    } while (0)

    // ---- prologue: B chunk 0 into stage 0, stage B chunk 1 in regs ----
    LOAD_B(0);
    STORE_B(0);
    LOAD_B(1);

    #pragma unroll 1
    for (int c = 0; c < NCH; c++) {
        const int cur = c & 1;
        const int nxt = (c + 1) & 1;

        GBAR();   // publishes B chunk c; closes reads of stage nxt

        // ---- A LDGs for chunk c (both k16 steps), straight into regs ----
        float2 ax[2][2][4];
        {
            const float* xc = xbase + c * CHK;
            #pragma unroll
            for (int mf = 0; mf < 2; mf++)
                #pragma unroll
                for (int s = 0; s < 2; s++)
                    #pragma unroll
                    for (int i = 0; i < 4; i++)
                        ax[mf][s][i] = *reinterpret_cast<const float2*>(
                            xc + (mf * 16 + (i & 1) * 8) * DDIM + s * 16 + (i >> 1) * 8);
        }

        if (c + 1 < NCH) STORE_B(nxt);
        if (c + 2 < NCH) LOAD_B(c + 2);

        const uint32_t bB = gB + cur * STG_SZ;
        #pragma unroll
        for (int s = 0; s < 2; s++) {
            // convert A fragments (registers only)
            uint32_t Ah[2][4], Al[2][4];
            #pragma unroll
            for (int mf = 0; mf < 2; mf++)
                #pragma unroll
                for (int i = 0; i < 4; i++)
                    split2h(ax[mf][s][i].x, ax[mf][s][i].y, Ah[mf][i], Al[mf][i]);
            // B fragments from smem
            uint32_t Bh[2][4], Bl[2][4];
            #pragma unroll
            for (int q = 0; q < 2; q++) {
                uint32_t base = bB + (uint32_t)(s * 16 * BROW) + b_lane
                              + (uint32_t)((n0 + q * 16) * 2);
                ldsm4t(Bh[q], base);
                ldsm4t(Bl[q], base + B_PL);
            }
            // term-major passes: hh, hl, lh
            #pragma unroll
            for (int mf = 0; mf < 2; mf++)
                #pragma unroll
                for (int nf = 0; nf < 4; nf++)
                    mma16816(acc[mf][nf], Ah[mf],
                             Bh[nf >> 1][(nf & 1) * 2], Bh[nf >> 1][(nf & 1) * 2 + 1]);
            #pragma unroll
            for (int mf = 0; mf < 2; mf++)
                #pragma unroll
                for (int nf = 0; nf < 4; nf++)
                    mma16816(acc[mf][nf], Ah[mf],
                             Bl[nf >> 1][(nf & 1) * 2], Bl[nf >> 1][(nf & 1) * 2 + 1]);
            #pragma unroll
            for (int mf = 0; mf < 2; mf++)
                #pragma unroll
                for (int nf = 0; nf < 4; nf++)
                    mma16816(acc[mf][nf], Al[mf],
                             Bh[nf >> 1][(nf & 1) * 2], Bh[nf >> 1][(nf & 1) * 2 + 1]);
        }
    }

    // ---- epilogue: write k-split partials ----
    float* gp = g_part + (long)ks * NTOK * 128;
    #pragma unroll
    for (int mf = 0; mf < 2; mf++) {
        int tok = (int)t0 + m0 + mf * 16 + (lane >> 2);
        #pragma unroll
        for (int nf = 0; nf < 4; nf++) {
            int col = grp * 64 + n0 + nf * 8 + (lane & 3) * 2;
            *reinterpret_cast<float2*>(&gp[(long)tok * 128 + col]) =
                make_float2(acc[mf][nf][0], acc[mf][nf][1]);
            *reinterpret_cast<float2*>(&gp[(long)(tok + 8) * 128 + col]) =
                make_float2(acc[mf][nf][2], acc[mf][nf][3]);
        }
    }

    // ---- arrival: second CTA of this tile (ks pair) runs the router ----
    __threadfence();
    __syncthreads();
    if (tid == 0) {
        int old = atomicAdd(&g_ctr[tile], 1);
        s_flag = (old == 1);
        if (old == 1) g_ctr[tile] = 0;   // self-reset for graph replay
    }
    __syncthreads();
    if (!s_flag) return;
    __threadfence();   // acquire peer CTA's partials

    #pragma unroll 1
    for (int i = 0; i < 8; i++) {
        long t = t0 + wid * 8 + i;
        const float* P0 = g_part + t * 128;
        const float* P1 = g_part + (NTOK + t) * 128;
        float g0 = P0[lane]       + P1[lane];
        float g1 = P0[lane + 32]  + P1[lane + 32];
        float n0v = P0[64 + lane] + P1[64 + lane];
        float n1v = P0[96 + lane] + P1[96 + lane];
        float l0 = g0 + softplus_f(n0v) * eps[t * NE + lane];
        float l1 = g1 + softplus_f(n1v) * eps[t * NE + lane + 32];

        float v1, v2; int i1, i2;
        if (l0 >= l1) { v1 = l0; i1 = lane;      v2 = l1; i2 = lane + 32; }
        else          { v1 = l1; i1 = lane + 32; v2 = l0; i2 = lane; }
        #pragma unroll
        for (int off = 16; off; off >>= 1) {
            float ov1 = __shfl_xor_sync(0xffffffffu, v1, off);
            int   oi1 = __shfl_xor_sync(0xffffffffu, i1, off);
            float ov2 = __shfl_xor_sync(0xffffffffu, v2, off);
            int   oi2 = __shfl_xor_sync(0xffffffffu, i2, off);
            top2_merge(v1, i1, v2, i2, ov1, oi1, ov2, oi2);
        }

        float e  = expf(v2 - v1);
        float p1 = 1.0f / (1.0f + e);
        float p2 = e * p1;

        float pr0 = (lane == i1) ? p1 : ((lane == i2) ? p2 : 0.0f);
        float pr1 = ((lane + 32) == i1) ? p1 : (((lane + 32) == i2) ? p2 : 0.0f);
        out[P_OFF + t * NE + lane]      = pr0;
        out[P_OFF + t * NE + lane + 32] = pr1;
        if (lane == 0) {
            out[I_OFF + t * 2 + 0] = (float)i1;
            out[I_OFF + t * 2 + 1] = (float)i2;
        }
        out[M_OFF + t * NE + lane]      = (lane == i1) ? 1.0f : 0.0f;
        out[M_OFF + t * NE + lane + 32] = ((lane + 32) == i1) ? 1.0f : 0.0f;
        out[M_OFF + (long)NTOK * NE + t * NE + lane]      = (lane == i2) ? 1.0f : 0.0f;
        out[M_OFF + (long)NTOK * NE + t * NE + lane + 32] = ((lane + 32) == i2) ? 1.0f : 0.0f;
    }
}

extern "C" void kernel_launch(void* const* d_in, const int* in_sizes, int n_in,
                              void* d_out, int out_size)
{
    const float* x   = (const float*)d_in[0];  // [4,2048,2048]
    const float* eps = (const float*)d_in[1];  // [4,2048,64]
    const float* wg  = (const float*)d_in[2];  // [2048,64]
    const float* wn  = (const float*)d_in[3];  // [2048,64]
    float* out = (float*)d_out;

    cudaFuncSetAttribute(gemm_fused, cudaFuncAttributeMaxDynamicSharedMemorySize, SMEMB);
    gemm_fused<<<128, 512, SMEMB>>>(x, wg, wn, eps, out);
}

// round 10
// speedup vs baseline: 1.3917x; 1.3917x over previous
#include <cuda_runtime.h>
#include <cuda_fp16.h>
#include <cstdint>
#include <cmath>

// ---------------- problem constants ----------------
#define NTOK 8192      // B*T
#define DDIM 2048
#define NE   64

// output layout (concatenated float32)
#define P_OFF 0
#define I_OFF (NTOK * NE)
#define M_OFF (I_OFF + NTOK * 2)

// ---------------- GEMM tiling (R4-proven) ----------------
#define KSPLIT 2
#define KQ     1024           // K per split
#define CHK    32             // k per chunk
#define NCH    32             // chunks (KQ/CHK)
#define AROW   80             // smem row stride bytes (64B data + 16B pad)
#define A_PL   (128 * AROW)   // A plane: 128 tokens (10240)
#define B_PL   (128 * AROW)   // B plane: 128 cols   (10240)
#define A_SZ   (2 * A_PL)     // 20480
#define B_SZ   (2 * B_PL)     // 20480
#define BUF    (A_SZ + B_SZ)  // 40960
#define SMEMB  (2 * BUF)      // 81920, double buffered

// ---------------- scratch ----------------
__device__ __align__(16) __half g_B[2 * 128 * 2048];   // [plane][col][k] fp16
__device__ float g_part[KSPLIT * NTOK * 128];          // k-split partials (8MB)
__device__ int   g_ctr[64];                            // per-tile counters (self-reset)

// ---------------- helpers ----------------
__device__ __forceinline__ uint32_t smem_u32(const void* p) {
    uint32_t a;
    asm("{ .reg .u64 t; cvta.to.shared.u64 t, %1; cvt.u32.u64 %0, t; }" : "=r"(a) : "l"(p));
    return a;
}
#define CP16(dst, src) \
    asm volatile("cp.async.cg.shared.global [%0], [%1], 16;" :: "r"(dst), "l"(src) : "memory")
#define CP_COMMIT() asm volatile("cp.async.commit_group;" ::: "memory")
#define CP_WAIT0()  asm volatile("cp.async.wait_group 0;" ::: "memory")

__device__ __forceinline__ void ldsm4(uint32_t (&r)[4], uint32_t addr) {
    asm volatile("ldmatrix.sync.aligned.m8n8.x4.shared.b16 {%0,%1,%2,%3}, [%4];"
                 : "=r"(r[0]), "=r"(r[1]), "=r"(r[2]), "=r"(r[3]) : "r"(addr));
}
__device__ __forceinline__ void mma16816(float (&c)[4], const uint32_t (&a)[4],
                                         uint32_t b0, uint32_t b1) {
    asm volatile(
        "mma.sync.aligned.m16n8k16.row.col.f32.f16.f16.f32 "
        "{%0,%1,%2,%3},{%4,%5,%6,%7},{%8,%9},{%0,%1,%2,%3};"
        : "+f"(c[0]), "+f"(c[1]), "+f"(c[2]), "+f"(c[3])
        : "r"(a[0]), "r"(a[1]), "r"(a[2]), "r"(a[3]), "r"(b0), "r"(b1));
}
__device__ __forceinline__ uint32_t h2_bits(__half2 v) {
    return *reinterpret_cast<uint32_t*>(&v);
}
// split 8 fp32 -> 2 planes of 8 fp16 (packed uint4 each)
__device__ __forceinline__ void split8h(const float* f, uint4& H, uint4& L) {
    uint32_t hw[4], lw[4];
    #pragma unroll
    for (int i = 0; i < 4; i++) {
        float a = f[2 * i], b = f[2 * i + 1];
        __half2 hp = __floats2half2_rn(a, b);
        float ra = a - __low2float(hp);
        float rb = b - __high2float(hp);
        __half2 lp = __floats2half2_rn(ra, rb);
        hw[i] = h2_bits(hp); lw[i] = h2_bits(lp);
    }
    H = make_uint4(hw[0], hw[1], hw[2], hw[3]);
    L = make_uint4(lw[0], lw[1], lw[2], lw[3]);
}
__device__ __forceinline__ float softplus_f(float v) {
    return (v > 20.0f) ? v : log1pf(expf(v));
}
__device__ __forceinline__ void top2_merge(float& v1, int& i1, float& v2, int& i2,
                                           float ov1, int oi1, float ov2, int oi2) {
    bool ow = (ov1 > v1) || (ov1 == v1 && oi1 < i1);
    float nv1 = ow ? ov1 : v1;  int ni1 = ow ? oi1 : i1;
    float lv  = ow ? v1  : ov1; int li  = ow ? i1  : oi1;
    float wv2 = ow ? ov2 : v2;  int wi2 = ow ? oi2 : i2;
    bool sw = (lv > wv2) || (lv == wv2 && li < wi2);
    v1 = nv1; i1 = ni1;
    v2 = sw ? lv : wv2; i2 = sw ? li : wi2;
}

// ---------------- prep: w -> g_B[2][128 col][2048 k] fp16, smem transpose ----------------
// grid 128: blockIdx = kc*2 + h. Each block: one matrix, 32 k, 64 experts.
__global__ __launch_bounds__(256) void prep_b(const float* __restrict__ wg,
                                              const float* __restrict__ wn) {
    __shared__ __align__(16) __half sh[2][64][36];  // [plane][n][32k + pad]
    const int tid = threadIdx.x;
    const int h  = blockIdx.x & 1;
    const int k0 = (blockIdx.x >> 1) * 32;
    const float* w = h ? wn : wg;

    // phase 1: coalesced reads, split, transposed smem store
    #pragma unroll
    for (int i = 0; i < 8; i++) {
        int fid = i * 256 + tid;            // 0..2047
        int kk = fid >> 6;                  // 0..31
        int n  = fid & 63;
        float a = w[(k0 + kk) * 64 + n];
        __half hh = __float2half_rn(a);
        __half hl = __float2half_rn(a - __half2float(hh));
        sh[0][n][kk] = hh;
        sh[1][n][kk] = hl;
    }
    __syncthreads();

    // phase 2: coalesced 8B writes to gmem
    #pragma unroll
    for (int i = 0; i < 4; i++) {
        int fid = i * 256 + tid;            // 0..1023
        int plane = fid >> 9;
        int rem = fid & 511;
        int row = rem >> 3;                 // 0..63
        int kq  = rem & 7;                  // 8 slots of 4 halves
        uint2 v = *reinterpret_cast<const uint2*>(&sh[plane][row][kq * 4]);
        *reinterpret_cast<uint2*>(&g_B[(plane * 128 + h * 64 + row) * 2048 + k0 + kq * 4]) = v;
    }
}

// ---------------- fused GEMM + router ----------------
__global__ __launch_bounds__(512, 1) void gemm_fused(
    const float* __restrict__ x, const float* __restrict__ eps,
    float* __restrict__ out)
{
    extern __shared__ char smem[];
    __shared__ int s_flag;
    const uint32_t sb = smem_u32(smem);
    const int tid  = threadIdx.x;
    const int wid  = tid >> 5;
    const int lane = tid & 31;
    const int tile = blockIdx.x >> 1;
    const int ks   = blockIdx.x & 1;
    const long t0  = (long)tile * 128;
    const int kbase = ks * KQ;

    const int m0  = (wid & 3) * 32;    // warp m-group
    const int n0w = (wid >> 2) * 32;   // warp n-group

    const int am = tid >> 2;           // A fill: token row (0..127)
    const int aq = tid & 3;            // A fill: 16B slot (8 k)

    float acc[2][4][4];
    #pragma unroll
    for (int a = 0; a < 2; a++)
        #pragma unroll
        for (int b = 0; b < 4; b++)
            #pragma unroll
            for (int c = 0; c < 4; c++) acc[a][b][c] = 0.0f;

    const int t4 = lane >> 3, r8 = lane & 7;
    const uint32_t a_lane = (uint32_t)(((t4 & 1) * 8 + r8) * AROW + (t4 >> 1) * 16);
    const uint32_t b_lane = (uint32_t)(((t4 >> 1) * 8 + r8) * AROW + (t4 & 1) * 16);

    float4 sxa, sxb;   // staged A chunk (x only; B goes via cp.async)

    #define LOAD_A(ch) do {                                                            \
        const float4* px = reinterpret_cast<const float4*>(                            \
            x + (t0 + am) * DDIM + kbase + (ch) * CHK + aq * 8);                       \
        sxa = px[0]; sxb = px[1];                                                      \
    } while (0)

    #define STORE_A(buf) do {                                                          \
        uint4 H, L;                                                                    \
        float f[8] = {sxa.x, sxa.y, sxa.z, sxa.w, sxb.x, sxb.y, sxb.z, sxb.w};         \
        split8h(f, H, L);                                                              \
        *reinterpret_cast<uint4*>(smem + (buf) + 0 * A_PL + am * AROW + aq * 16) = H;  \
        *reinterpret_cast<uint4*>(smem + (buf) + 1 * A_PL + am * AROW + aq * 16) = L;  \
    } while (0)

    #define CPASYNC_B(buf, ch) do {                                                    \
        int k0c = kbase + (ch) * CHK;                                                  \
        _Pragma("unroll")                                                              \
        for (int i = 0; i < 2; i++) {                                                  \
            int seg = tid + 512 * i;                                                   \
            int plane = seg >> 9, rem = seg & 511, row = rem >> 2, kq = rem & 3;       \
            const __half* src = g_B + (plane * 128 + row) * 2048 + k0c + kq * 8;       \
            CP16(sb + (buf) + A_SZ + plane * B_PL + row * AROW + kq * 16, src);        \
        }                                                                              \
        CP_COMMIT();                                                                   \
    } while (0)

    // ---- prologue ----
    LOAD_A(0);
    STORE_A(0u);
    CPASYNC_B(0u, 0);
    LOAD_A(1);

    #pragma unroll 1
    for (int c = 0; c < NCH; c++) {
        const uint32_t cur = (uint32_t)((c & 1) * BUF);
        const uint32_t nxt = (uint32_t)(((c + 1) & 1) * BUF);

        CP_WAIT0();        // B buffer c landed
        __syncthreads();   // A stores of c visible; reads of buffer nxt (c-1) done

        if (c + 1 < NCH) {
            STORE_A(nxt);
            CPASYNC_B(nxt, c + 1);
        }
        if (c + 2 < NCH) LOAD_A(c + 2);

        const uint32_t aB = sb + cur;
        const uint32_t bB = sb + cur + A_SZ;
        #pragma unroll
        for (int s = 0; s < 2; s++) {
            uint32_t Ah[2][4], Al[2][4], Bh[2][4], Bl[2][4];
            #pragma unroll
            for (int mf = 0; mf < 2; mf++) {
                uint32_t base = aB + (uint32_t)((m0 + mf * 16) * AROW) + a_lane + s * 32;
                ldsm4(Ah[mf], base);
                ldsm4(Al[mf], base + A_PL);
            }
            #pragma unroll
            for (int q = 0; q < 2; q++) {
                uint32_t base = bB + (uint32_t)((n0w + q * 16) * AROW) + b_lane + s * 32;
                ldsm4(Bh[q], base);
                ldsm4(Bl[q], base + B_PL);
            }
            // term-major: hh, hl, lh
            #pragma unroll
            for (int mf = 0; mf < 2; mf++)
                #pragma unroll
                for (int nf = 0; nf < 4; nf++)
                    mma16816(acc[mf][nf], Ah[mf],
                             Bh[nf >> 1][(nf & 1) * 2], Bh[nf >> 1][(nf & 1) * 2 + 1]);
            #pragma unroll
            for (int mf = 0; mf < 2; mf++)
                #pragma unroll
                for (int nf = 0; nf < 4; nf++)
                    mma16816(acc[mf][nf], Ah[mf],
                             Bl[nf >> 1][(nf & 1) * 2], Bl[nf >> 1][(nf & 1) * 2 + 1]);
            #pragma unroll
            for (int mf = 0; mf < 2; mf++)
                #pragma unroll
                for (int nf = 0; nf < 4; nf++)
                    mma16816(acc[mf][nf], Al[mf],
                             Bh[nf >> 1][(nf & 1) * 2], Bh[nf >> 1][(nf & 1) * 2 + 1]);
        }
    }

    // ---- epilogue: write k-split partials ----
    float* gp = g_part + (long)ks * NTOK * 128;
    #pragma unroll
    for (int mf = 0; mf < 2; mf++) {
        int tok = (int)t0 + m0 + mf * 16 + (lane >> 2);
        #pragma unroll
        for (int nf = 0; nf < 4; nf++) {
            int col = n0w + nf * 8 + (lane & 3) * 2;
            *reinterpret_cast<float2*>(&gp[(long)tok * 128 + col]) =
                make_float2(acc[mf][nf][0], acc[mf][nf][1]);
            *reinterpret_cast<float2*>(&gp[(long)(tok + 8) * 128 + col]) =
                make_float2(acc[mf][nf][2], acc[mf][nf][3]);
        }
    }

    // ---- arrival: second CTA of this tile runs the router ----
    __threadfence();
    if (tid == 0) {
        int old = atomicAdd(&g_ctr[tile], 1);
        s_flag = (old == 1);
        if (old == 1) g_ctr[tile] = 0;   // self-reset for graph replay
    }
    __syncthreads();
    if (!s_flag) return;
    __threadfence();   // acquire peer CTA's partials

    #pragma unroll 1
    for (int i = 0; i < 8; i++) {
        long t = t0 + wid * 8 + i;
        const float* P0 = g_part + t * 128;
        const float* P1 = g_part + (NTOK + t) * 128;
        float g0 = P0[lane]       + P1[lane];
        float g1 = P0[lane + 32]  + P1[lane + 32];
        float n0 = P0[64 + lane]  + P1[64 + lane];
        float n1 = P0[96 + lane]  + P1[96 + lane];
        float l0 = g0 + softplus_f(n0) * eps[t * NE + lane];
        float l1 = g1 + softplus_f(n1) * eps[t * NE + lane + 32];

        float v1, v2; int i1, i2;
        if (l0 >= l1) { v1 = l0; i1 = lane;      v2 = l1; i2 = lane + 32; }
        else          { v1 = l1; i1 = lane + 32; v2 = l0; i2 = lane; }
        #pragma unroll
        for (int off = 16; off; off >>= 1) {
            float ov1 = __shfl_xor_sync(0xffffffffu, v1, off);
            int   oi1 = __shfl_xor_sync(0xffffffffu, i1, off);
            float ov2 = __shfl_xor_sync(0xffffffffu, v2, off);
            int   oi2 = __shfl_xor_sync(0xffffffffu, i2, off);
            top2_merge(v1, i1, v2, i2, ov1, oi1, ov2, oi2);
        }

        float e  = expf(v2 - v1);
        float p1 = 1.0f / (1.0f + e);
        float p2 = e * p1;

        float pr0 = (lane == i1) ? p1 : ((lane == i2) ? p2 : 0.0f);
        float pr1 = ((lane + 32) == i1) ? p1 : (((lane + 32) == i2) ? p2 : 0.0f);
        out[P_OFF + t * NE + lane]      = pr0;
        out[P_OFF + t * NE + lane + 32] = pr1;
        if (lane == 0) {
            out[I_OFF + t * 2 + 0] = (float)i1;
            out[I_OFF + t * 2 + 1] = (float)i2;
        }
        out[M_OFF + t * NE + lane]      = (lane == i1) ? 1.0f : 0.0f;
        out[M_OFF + t * NE + lane + 32] = ((lane + 32) == i1) ? 1.0f : 0.0f;
        out[M_OFF + (long)NTOK * NE + t * NE + lane]      = (lane == i2) ? 1.0f : 0.0f;
        out[M_OFF + (long)NTOK * NE + t * NE + lane + 32] = ((lane + 32) == i2) ? 1.0f : 0.0f;
    }
}

extern "C" void kernel_launch(void* const* d_in, const int* in_sizes, int n_in,
                              void* d_out, int out_size)
{
    const float* x   = (const float*)d_in[0];  // [4,2048,2048]
    const float* eps = (const float*)d_in[1];  // [4,2048,64]
    const float* wg  = (const float*)d_in[2];  // [2048,64]
    const float* wn  = (const float*)d_in[3];  // [2048,64]
    float* out = (float*)d_out;

    cudaFuncSetAttribute(gemm_fused, cudaFuncAttributeMaxDynamicSharedMemorySize, SMEMB);
    prep_b<<<128, 256>>>(wg, wn);
    gemm_fused<<<128, 512, SMEMB>>>(x, eps, out);
}